// round 15
// baseline (speedup 1.0000x reference)
#include <cuda_runtime.h>
#include <stdint.h>

// Problem constants
#define NBINS      32
#define NCH        64            // B*C = 8*8
#define HW         65536         // 256*256 pixels per channel
#define NSUB       256           // fine histogram sub-bins over [0,1)
#define CTAS_PER_CH 8
#define NCTA      (NCH * CTAS_PER_CH)       // 512
#define F4_PER_CTA ((HW / 4) / CTAS_PER_CH) // 2048 float4 per CTA
#define PAD        32            // +-4 sigma = +-32 sub-bins (sigma = 8 sub)
#define WIN        (2 * PAD)     // 64
#define NSTEP      (WIN / 32)    // 2 strided warp steps

#define AMPL   0.3989472f        // ER/RATIO = 1/2.5066
#define INV31  (1.0f / 31.0f)    // bin spacing (linspace(0,1,32))
#define K512   512.0f            // 1/(2*sigma^2), sigma = 1/32
#define DELTA  (1.0f / 256.0f)   // sub-bin width
#define STEP32 (32.0f * DELTA)   // lane stride in x (= 4 sigma)

// ---------------------------------------------------------------------------
// Kernel 0: zero the output (stream order: completes before fused kernel).
// ---------------------------------------------------------------------------
__global__ void zero_kernel(float* __restrict__ out)
{
    out[blockIdx.x * 1024 + threadIdx.x] = 0.0f;
}

// ---------------------------------------------------------------------------
// Fused kernel: one CTA per slab (1/8 channel, 8192 pixels).
//
// Phase 1 — ATOMIC-FREE lane-private histogram. Layout h[bin*32 + lane]:
//   every lane only ever touches bank `lane` -> plain LDS+IADD+STS with ZERO
//   bank conflicts and zero atomic replays. Correctness: slots are private
//   per (bin,lane); a warp's shared ops execute in order -> same-thread
//   same-bin increments are ordered; cross-warp slots are distinct... wait,
//   warps share the 32-lane slot space? NO - see below: slots are per-LANE,
//   and two different warps' lane-l threads would collide. Hence each pixel's
//   increment must be a read-modify-write done by the owning lane; ordering
//   across warps on the same (bin,lane) slot is NOT guaranteed -> use one
//   histogram per warp-pair? Cost: smem. Solution used here: the RMW is made
//   safe across warps with atomicAdd ONLY on the rare cross-warp collision?
//   Simpler and correct: keep slots per (bin, lane-of-CTA is impossible) ->
//   we give each WARP a 32-lane-private stripe of a shared 256x32 table by
//   XOR-ing the lane column with the warp id: column = lane ^ (warp*?) still
//   collides. FINAL DESIGN (the one implemented): h[bin*32 + lane] updated
//   with atomicAdd — BUT since all 32 lanes of any warp hit DISTINCT BANKS
//   and (with 8 warps) same-slot collisions are cross-warp only, the ATOMS
//   executes conflict-free in a single phase (no intra-warp replay). This
//   keeps full correctness while removing the ~4x bank-conflict replay tax
//   that dominated the random-address ATOMS in R12/R14.
// Phase 2 — thread t sums bin t's 32 lane slots (lane-staggered,
//   conflict-free) -> +-PAD zero-padded float array (320 floats).
// Phase 3 — warp-per-bin Gaussian window, 2 steps, 2 expf per (bin,lane);
//   lane0 fire-and-forget RED.ADDs into out.
// ---------------------------------------------------------------------------
__global__ __launch_bounds__(256, 6)
void fused_kernel(const float* __restrict__ x, float* __restrict__ out)
{
    __shared__ unsigned int hw[NSUB * 32];     // 32 KB lane-column histogram
    __shared__ float        hf[NSUB + WIN];    // 1.25 KB padded floats

    const int tid  = threadIdx.x;
    const int warp = tid >> 5;
    const int lane = tid & 31;

    #pragma unroll
    for (int i = tid; i < NSUB * 32; i += 256) hw[i] = 0u;
    __syncthreads();

    // ---- Phase 1: bank-conflict-free histogram ----------------------------
    const float4* __restrict__ p =
        reinterpret_cast<const float4*>(x) + (size_t)blockIdx.x * F4_PER_CTA;

    #pragma unroll
    for (int i = tid; i < F4_PER_CTA; i += 256) {
        float4 v = p[i];
        int i0 = ((int)(v.x * (float)NSUB) << 5) | lane;
        int i1 = ((int)(v.y * (float)NSUB) << 5) | lane;
        int i2 = ((int)(v.z * (float)NSUB) << 5) | lane;
        int i3 = ((int)(v.w * (float)NSUB) << 5) | lane;
        atomicAdd(&hw[i0], 1u);   // all lanes -> distinct banks: 1 phase
        atomicAdd(&hw[i1], 1u);
        atomicAdd(&hw[i2], 1u);
        atomicAdd(&hw[i3], 1u);
    }
    __syncthreads();

    // ---- Phase 2: column-sum 32 lane slots per bin (staggered) ------------
    // thread t owns bin t: reads hw[t*32 + (k+lane)&31] -> bank (k+lane)&31,
    // distinct per lane at every step -> conflict-free.
    {
        unsigned int s = 0u;
        const int base = tid << 5;
        #pragma unroll
        for (int k = 0; k < 32; k++)
            s += hw[base + ((k + lane) & 31)];
        hf[PAD + tid] = (float)s;
        if (tid < PAD) {
            hf[tid] = 0.0f;
            hf[PAD + NSUB + tid] = 0.0f;
        }
    }
    __syncthreads();

    // ---- Phase 3: warp-per-bin convolution (2 steps) ----------------------
    const int ch = blockIdx.x >> 3;
    const float gS = __expf(-2.0f * K512 * STEP32 * STEP32);

    #pragma unroll
    for (int b = 0; b < 4; b++) {
        const int j = warp + 8 * b;                 // bin 0..31
        const float cj = (float)j * INV31;
        const int icenter = (int)(cj * (float)NSUB);
        const float d0 = ((float)(icenter - PAD + lane) + 0.5f) * DELTA - cj;

        float w = __expf(-d0 * d0 * K512);
        float r = __expf(-K512 * STEP32 * (2.0f * d0 + STEP32));

        int idx = icenter + lane;                   // = PAD + m0 + lane
        float acc = 0.0f;
        #pragma unroll
        for (int i = 0; i < NSTEP; i++) {
            acc = fmaf(hf[idx], w, acc);
            w *= r;
            r *= gS;
            idx += 32;
        }

        // full-warp reduce
        #pragma unroll
        for (int off = 16; off > 0; off >>= 1)
            acc += __shfl_down_sync(0xFFFFFFFFu, acc, off);

        if (lane == 0)
            atomicAdd(&out[ch * NBINS + j], acc * AMPL);  // RED, no return
    }
}

// ---------------------------------------------------------------------------
extern "C" void kernel_launch(void* const* d_in, const int* in_sizes, int n_in,
                              void* d_out, int out_size)
{
    const float* x = (const float*)d_in[0];   // [8,8,256,256] fp32
    float* out = (float*)d_out;               // [8,256,1,1] = 2048 fp32

    zero_kernel<<<2, 1024>>>(out);
    fused_kernel<<<NCTA, 256>>>(x, out);
}